// round 2
// baseline (speedup 1.0000x reference)
#include <cuda_runtime.h>
#include <cuda_bf16.h>
#include <math.h>

// Window attention (Swin-style), fully fused: one CTA per window.
// Shapes: x(2048,49,256), mask(64,49,49), qkv_w(768,256), qkv_b(768),
//         proj_w(256,256), proj_b(256), rpb_table(169,8), rel_index(49,49)
// out: (2048,49,256) fp32

#define BWIN 2048
#define NTOK 49
#define NPAD 56           // 8 row-groups * 7 rows
#define DIMC 256
#define NHEAD 8
#define DH 32
#define NWMASK 64
#define WS_STRIDE 260     // padded ws row (floats): conflict-free LDS.128
#define QKV_STRIDE 36     // padded q/k/v row
#define ATT_STRIDE 52     // padded attn row (16B-aligned row base)
#define NREL 169

struct SM {
    float xs[NPAD * DIMC];            // 57344 B
    float ws[DH * WS_STRIDE];         // 33280 B (weight slice staging)
    float qs[NPAD * QKV_STRIDE];      // 8064 B
    float ks[NPAD * QKV_STRIDE];
    float vs[NPAD * QKV_STRIDE];
    float attn[NPAD * ATT_STRIDE];    // 11648 B
    float outp[NPAD * DIMC];          // 57344 B (pre-projection concat heads)
    int   relidx[NTOK * NTOK];
    float rpbt[NREL * NHEAD];
    float maskw[NTOK * NTOK];
};

__global__ __launch_bounds__(256, 1)
void window_attn_fused(const float* __restrict__ x,
                       const float* __restrict__ mask,
                       const float* __restrict__ qkv_w,
                       const float* __restrict__ qkv_b,
                       const float* __restrict__ proj_w,
                       const float* __restrict__ proj_b,
                       const float* __restrict__ rpb_table,
                       const int*   __restrict__ rel_index,
                       float* __restrict__ out)
{
    extern __shared__ __align__(16) unsigned char smem_raw[];
    SM& sm = *reinterpret_cast<SM*>(smem_raw);

    const int tid  = threadIdx.x;
    const int b    = blockIdx.x;
    const int w    = b & (NWMASK - 1);          // window index within image
    const int c    = tid & 31;                  // column within a 32-col slice
    const int rg   = tid >> 5;                  // row group 0..7
    const int r0   = rg * 7;                    // rows r0..r0+6 (rg=7 -> padded rows)
    const float scale = 0.17677669529663687f;   // 32^-0.5

    // ---------- Phase 0: stage x, rel_index, rpb_table, mask ----------
    {
        const float4* xg = reinterpret_cast<const float4*>(x + (size_t)b * NTOK * DIMC);
        float4* xsv = reinterpret_cast<float4*>(sm.xs);
        #pragma unroll 4
        for (int i = tid; i < NTOK * (DIMC / 4); i += 256) xsv[i] = xg[i];
        const float4 z4 = make_float4(0.f, 0.f, 0.f, 0.f);
        for (int i = tid; i < (NPAD - NTOK) * (DIMC / 4); i += 256)
            xsv[NTOK * (DIMC / 4) + i] = z4;

        for (int i = tid; i < NTOK * NTOK; i += 256) {
            sm.relidx[i] = rel_index[i];
            sm.maskw[i]  = mask[(size_t)w * NTOK * NTOK + i];
        }
        for (int i = tid; i < NREL * NHEAD; i += 256) sm.rpbt[i] = rpb_table[i];
    }
    __syncthreads();

    // ---------- Per-head attention ----------
    for (int h = 0; h < NHEAD; ++h) {
        // -- compute q, k, v (each 49x32) for this head --
        for (int s = 0; s < 3; ++s) {
            __syncthreads();   // previous readers of ws / qs / ks / vs done
            // stage weight slice: 32 rows x 256 cols of qkv_w
            const float* wsrc = qkv_w + (size_t)(s * DIMC + h * DH) * DIMC;
            for (int i = tid; i < DH * (DIMC / 4); i += 256) {
                int row = i >> 6, kq = i & 63;
                float4 g = reinterpret_cast<const float4*>(wsrc + row * DIMC)[kq];
                *reinterpret_cast<float4*>(&sm.ws[row * WS_STRIDE + kq * 4]) = g;
            }
            __syncthreads();

            float acc[7];
            const float bias = qkv_b[s * DIMC + h * DH + c];
            #pragma unroll
            for (int i = 0; i < 7; ++i) acc[i] = bias;

            #pragma unroll 4
            for (int k = 0; k < DIMC; k += 4) {
                float4 wv = *reinterpret_cast<const float4*>(&sm.ws[c * WS_STRIDE + k]);
                #pragma unroll
                for (int i = 0; i < 7; ++i) {
                    float4 xv = *reinterpret_cast<const float4*>(&sm.xs[(r0 + i) * DIMC + k]);
                    acc[i] += xv.x * wv.x + xv.y * wv.y + xv.z * wv.z + xv.w * wv.w;
                }
            }
            float* dst = (s == 0) ? sm.qs : (s == 1) ? sm.ks : sm.vs;
            const float mul = (s == 0) ? scale : 1.0f;
            #pragma unroll
            for (int i = 0; i < 7; ++i) dst[(r0 + i) * QKV_STRIDE + c] = acc[i] * mul;
        }
        __syncthreads();

        // -- attention scores: attn[n][m] = q_n . k_m + rpb + mask --
        for (int j = tid; j < NTOK * NTOK; j += 256) {
            const int n = j / NTOK;
            const int m = j - n * NTOK;
            float a = 0.f;
            #pragma unroll
            for (int d = 0; d < DH; d += 4) {
                float4 qv = *reinterpret_cast<const float4*>(&sm.qs[n * QKV_STRIDE + d]);
                float4 kv = *reinterpret_cast<const float4*>(&sm.ks[m * QKV_STRIDE + d]);
                a += qv.x * kv.x + qv.y * kv.y + qv.z * kv.z + qv.w * kv.w;
            }
            a += sm.rpbt[sm.relidx[j] * NHEAD + h] + sm.maskw[j];
            sm.attn[n * ATT_STRIDE + m] = a;
        }
        __syncthreads();

        // -- softmax per row (warp per row, rows strided by 8) --
        {
            const int lane = tid & 31;
            const int wid  = tid >> 5;
            for (int r = wid; r < NTOK; r += 8) {
                float* row = &sm.attn[r * ATT_STRIDE];
                float v1 = row[lane];
                float v2 = (lane + 32 < NTOK) ? row[lane + 32] : -INFINITY;
                float vmax = fmaxf(v1, v2);
                #pragma unroll
                for (int o = 16; o > 0; o >>= 1)
                    vmax = fmaxf(vmax, __shfl_xor_sync(0xffffffffu, vmax, o));
                float e1 = __expf(v1 - vmax);
                float e2 = (lane + 32 < NTOK) ? __expf(v2 - vmax) : 0.f;
                float ssum = e1 + e2;
                #pragma unroll
                for (int o = 16; o > 0; o >>= 1)
                    ssum += __shfl_xor_sync(0xffffffffu, ssum, o);
                float inv = __frcp_rn(ssum);
                row[lane] = e1 * inv;
                if (lane + 32 < NTOK) row[lane + 32] = e2 * inv;
            }
        }
        __syncthreads();

        // -- O_h = attn @ v  -> outp[:, h*32 + c] --
        {
            float acc[7];
            #pragma unroll
            for (int i = 0; i < 7; ++i) acc[i] = 0.f;
            #pragma unroll 3
            for (int m = 0; m < 48; m += 4) {
                float vv0 = sm.vs[(m + 0) * QKV_STRIDE + c];
                float vv1 = sm.vs[(m + 1) * QKV_STRIDE + c];
                float vv2 = sm.vs[(m + 2) * QKV_STRIDE + c];
                float vv3 = sm.vs[(m + 3) * QKV_STRIDE + c];
                #pragma unroll
                for (int i = 0; i < 7; ++i) {
                    float4 av = *reinterpret_cast<const float4*>(&sm.attn[(r0 + i) * ATT_STRIDE + m]);
                    acc[i] += av.x * vv0 + av.y * vv1 + av.z * vv2 + av.w * vv3;
                }
            }
            float v48 = sm.vs[48 * QKV_STRIDE + c];
            #pragma unroll
            for (int i = 0; i < 7; ++i) {
                acc[i] += sm.attn[(r0 + i) * ATT_STRIDE + 48] * v48;
                sm.outp[(r0 + i) * DIMC + h * DH + c] = acc[i];
            }
        }
        // loop-top __syncthreads() (inside s-loop) protects reuse
    }

    // ---------- Projection: out = outp @ proj_w^T + proj_b ----------
    for (int pc = 0; pc < DIMC / DH; ++pc) {
        __syncthreads();
        const float* wsrc = proj_w + (size_t)(pc * DH) * DIMC;
        for (int i = tid; i < DH * (DIMC / 4); i += 256) {
            int row = i >> 6, kq = i & 63;
            float4 g = reinterpret_cast<const float4*>(wsrc + row * DIMC)[kq];
            *reinterpret_cast<float4*>(&sm.ws[row * WS_STRIDE + kq * 4]) = g;
        }
        __syncthreads();

        float acc[7];
        const float bias = proj_b[pc * DH + c];
        #pragma unroll
        for (int i = 0; i < 7; ++i) acc[i] = bias;

        #pragma unroll 4
        for (int k = 0; k < DIMC; k += 4) {
            float4 wv = *reinterpret_cast<const float4*>(&sm.ws[c * WS_STRIDE + k]);
            #pragma unroll
            for (int i = 0; i < 7; ++i) {
                float4 xv = *reinterpret_cast<const float4*>(&sm.outp[(r0 + i) * DIMC + k]);
                acc[i] += xv.x * wv.x + xv.y * wv.y + xv.z * wv.z + xv.w * wv.w;
            }
        }
        if (rg < 7) {   // rows r0..r0+6 all < 49 only for rg 0..6
            float* og = out + (size_t)b * NTOK * DIMC;
            #pragma unroll
            for (int i = 0; i < 7; ++i)
                og[(r0 + i) * DIMC + pc * DH + c] = acc[i];
        }
    }
}

extern "C" void kernel_launch(void* const* d_in, const int* in_sizes, int n_in,
                              void* d_out, int out_size) {
    const float* x      = (const float*)d_in[0];
    const float* mask   = (const float*)d_in[1];
    const float* qkv_w  = (const float*)d_in[2];
    const float* qkv_b  = (const float*)d_in[3];
    const float* proj_w = (const float*)d_in[4];
    const float* proj_b = (const float*)d_in[5];
    const float* rpbt   = (const float*)d_in[6];
    const int*   relidx = (const int*)d_in[7];
    float* out = (float*)d_out;

    const int smem_bytes = (int)sizeof(SM);
    cudaFuncSetAttribute(window_attn_fused,
                         cudaFuncAttributeMaxDynamicSharedMemorySize, smem_bytes);

    window_attn_fused<<<BWIN, 256, smem_bytes>>>(
        x, mask, qkv_w, qkv_b, proj_w, proj_b, rpbt, relidx, out);
}

// round 4
// speedup vs baseline: 1.0003x; 1.0003x over previous
#include <cuda_runtime.h>
#include <cuda_bf16.h>
#include <math.h>

// Window attention (Swin-style), fully fused: one CTA per window.
// Shapes: x(2048,49,256), mask(64,49,49), qkv_w(768,256), qkv_b(768),
//         proj_w(256,256), proj_b(256), rpb_table(169,8), rel_index(49,49)
// out: (2048,49,256) fp32

#define BWIN 2048
#define NTOK 49
#define NPAD 56           // 8 row-groups * 7 rows
#define DIMC 256
#define NHEAD 8
#define DH 32
#define NWMASK 64
#define WS_STRIDE 260     // padded ws row (floats): conflict-free LDS.128
#define QKV_STRIDE 36     // padded q/k/v row
#define ATT_STRIDE 52     // padded attn row (16B-aligned row base)
#define NREL 169

struct SM {
    float xs[NPAD * DIMC];            // 57344 B
    float ws[DH * WS_STRIDE];         // 33280 B (weight slice staging)
    float qs[NPAD * QKV_STRIDE];      // 8064 B
    float ks[NPAD * QKV_STRIDE];
    float vs[NPAD * QKV_STRIDE];
    float attn[NPAD * ATT_STRIDE];    // 11648 B
    float outp[NPAD * DIMC];          // 57344 B (pre-projection concat heads)
    int   relidx[NTOK * NTOK];
    float rpbt[NREL * NHEAD];
    float maskw[NTOK * NTOK];
};

__global__ __launch_bounds__(256, 1)
void window_attn_fused(const float* __restrict__ x,
                       const float* __restrict__ mask,
                       const float* __restrict__ qkv_w,
                       const float* __restrict__ qkv_b,
                       const float* __restrict__ proj_w,
                       const float* __restrict__ proj_b,
                       const float* __restrict__ rpb_table,
                       const int*   __restrict__ rel_index,
                       float* __restrict__ out)
{
    extern __shared__ __align__(16) unsigned char smem_raw[];
    SM& sm = *reinterpret_cast<SM*>(smem_raw);

    const int tid  = threadIdx.x;
    const int b    = blockIdx.x;
    const int w    = b & (NWMASK - 1);          // window index within image
    const int c    = tid & 31;                  // column within a 32-col slice
    const int rg   = tid >> 5;                  // row group 0..7
    const int r0   = rg * 7;                    // rows r0..r0+6 (rg=7 -> padded rows)
    const float scale = 0.17677669529663687f;   // 32^-0.5

    // ---------- Phase 0: stage x, rel_index, rpb_table, mask ----------
    {
        const float4* xg = reinterpret_cast<const float4*>(x + (size_t)b * NTOK * DIMC);
        float4* xsv = reinterpret_cast<float4*>(sm.xs);
        #pragma unroll 4
        for (int i = tid; i < NTOK * (DIMC / 4); i += 256) xsv[i] = xg[i];
        const float4 z4 = make_float4(0.f, 0.f, 0.f, 0.f);
        for (int i = tid; i < (NPAD - NTOK) * (DIMC / 4); i += 256)
            xsv[NTOK * (DIMC / 4) + i] = z4;

        for (int i = tid; i < NTOK * NTOK; i += 256) {
            sm.relidx[i] = rel_index[i];
            sm.maskw[i]  = mask[(size_t)w * NTOK * NTOK + i];
        }
        for (int i = tid; i < NREL * NHEAD; i += 256) sm.rpbt[i] = rpb_table[i];
    }
    __syncthreads();

    // ---------- Per-head attention ----------
    for (int h = 0; h < NHEAD; ++h) {
        // -- compute q, k, v (each 49x32) for this head --
        for (int s = 0; s < 3; ++s) {
            __syncthreads();   // previous readers of ws / qs / ks / vs done
            // stage weight slice: 32 rows x 256 cols of qkv_w
            const float* wsrc = qkv_w + (size_t)(s * DIMC + h * DH) * DIMC;
            for (int i = tid; i < DH * (DIMC / 4); i += 256) {
                int row = i >> 6, kq = i & 63;
                float4 g = reinterpret_cast<const float4*>(wsrc + row * DIMC)[kq];
                *reinterpret_cast<float4*>(&sm.ws[row * WS_STRIDE + kq * 4]) = g;
            }
            __syncthreads();

            float acc[7];
            const float bias = qkv_b[s * DIMC + h * DH + c];
            #pragma unroll
            for (int i = 0; i < 7; ++i) acc[i] = bias;

            #pragma unroll 4
            for (int k = 0; k < DIMC; k += 4) {
                float4 wv = *reinterpret_cast<const float4*>(&sm.ws[c * WS_STRIDE + k]);
                #pragma unroll
                for (int i = 0; i < 7; ++i) {
                    float4 xv = *reinterpret_cast<const float4*>(&sm.xs[(r0 + i) * DIMC + k]);
                    acc[i] += xv.x * wv.x + xv.y * wv.y + xv.z * wv.z + xv.w * wv.w;
                }
            }
            float* dst = (s == 0) ? sm.qs : (s == 1) ? sm.ks : sm.vs;
            const float mul = (s == 0) ? scale : 1.0f;
            #pragma unroll
            for (int i = 0; i < 7; ++i) dst[(r0 + i) * QKV_STRIDE + c] = acc[i] * mul;
        }
        __syncthreads();

        // -- attention scores: attn[n][m] = q_n . k_m + rpb + mask --
        for (int j = tid; j < NTOK * NTOK; j += 256) {
            const int n = j / NTOK;
            const int m = j - n * NTOK;
            float a = 0.f;
            #pragma unroll
            for (int d = 0; d < DH; d += 4) {
                float4 qv = *reinterpret_cast<const float4*>(&sm.qs[n * QKV_STRIDE + d]);
                float4 kv = *reinterpret_cast<const float4*>(&sm.ks[m * QKV_STRIDE + d]);
                a += qv.x * kv.x + qv.y * kv.y + qv.z * kv.z + qv.w * kv.w;
            }
            a += sm.rpbt[sm.relidx[j] * NHEAD + h] + sm.maskw[j];
            sm.attn[n * ATT_STRIDE + m] = a;
        }
        __syncthreads();

        // -- softmax per row (warp per row, rows strided by 8) --
        {
            const int lane = tid & 31;
            const int wid  = tid >> 5;
            for (int r = wid; r < NTOK; r += 8) {
                float* row = &sm.attn[r * ATT_STRIDE];
                float v1 = row[lane];
                float v2 = (lane + 32 < NTOK) ? row[lane + 32] : -INFINITY;
                float vmax = fmaxf(v1, v2);
                #pragma unroll
                for (int o = 16; o > 0; o >>= 1)
                    vmax = fmaxf(vmax, __shfl_xor_sync(0xffffffffu, vmax, o));
                float e1 = __expf(v1 - vmax);
                float e2 = (lane + 32 < NTOK) ? __expf(v2 - vmax) : 0.f;
                float ssum = e1 + e2;
                #pragma unroll
                for (int o = 16; o > 0; o >>= 1)
                    ssum += __shfl_xor_sync(0xffffffffu, ssum, o);
                float inv = __frcp_rn(ssum);
                row[lane] = e1 * inv;
                if (lane + 32 < NTOK) row[lane + 32] = e2 * inv;
            }
        }
        __syncthreads();

        // -- O_h = attn @ v  -> outp[:, h*32 + c] --
        {
            float acc[7];
            #pragma unroll
            for (int i = 0; i < 7; ++i) acc[i] = 0.f;
            #pragma unroll 3
            for (int m = 0; m < 48; m += 4) {
                float vv0 = sm.vs[(m + 0) * QKV_STRIDE + c];
                float vv1 = sm.vs[(m + 1) * QKV_STRIDE + c];
                float vv2 = sm.vs[(m + 2) * QKV_STRIDE + c];
                float vv3 = sm.vs[(m + 3) * QKV_STRIDE + c];
                #pragma unroll
                for (int i = 0; i < 7; ++i) {
                    float4 av = *reinterpret_cast<const float4*>(&sm.attn[(r0 + i) * ATT_STRIDE + m]);
                    acc[i] += av.x * vv0 + av.y * vv1 + av.z * vv2 + av.w * vv3;
                }
            }
            float v48 = sm.vs[48 * QKV_STRIDE + c];
            #pragma unroll
            for (int i = 0; i < 7; ++i) {
                acc[i] += sm.attn[(r0 + i) * ATT_STRIDE + 48] * v48;
                sm.outp[(r0 + i) * DIMC + h * DH + c] = acc[i];
            }
        }
        // loop-top __syncthreads() (inside s-loop) protects reuse
    }

    // ---------- Projection: out = outp @ proj_w^T + proj_b ----------
    for (int pc = 0; pc < DIMC / DH; ++pc) {
        __syncthreads();
        const float* wsrc = proj_w + (size_t)(pc * DH) * DIMC;
        for (int i = tid; i < DH * (DIMC / 4); i += 256) {
            int row = i >> 6, kq = i & 63;
            float4 g = reinterpret_cast<const float4*>(wsrc + row * DIMC)[kq];
            *reinterpret_cast<float4*>(&sm.ws[row * WS_STRIDE + kq * 4]) = g;
        }
        __syncthreads();

        float acc[7];
        const float bias = proj_b[pc * DH + c];
        #pragma unroll
        for (int i = 0; i < 7; ++i) acc[i] = bias;

        #pragma unroll 4
        for (int k = 0; k < DIMC; k += 4) {
            float4 wv = *reinterpret_cast<const float4*>(&sm.ws[c * WS_STRIDE + k]);
            #pragma unroll
            for (int i = 0; i < 7; ++i) {
                float4 xv = *reinterpret_cast<const float4*>(&sm.outp[(r0 + i) * DIMC + k]);
                acc[i] += xv.x * wv.x + xv.y * wv.y + xv.z * wv.z + xv.w * wv.w;
            }
        }
        if (rg < 7) {   // rows r0..r0+6 all < 49 only for rg 0..6
            float* og = out + (size_t)b * NTOK * DIMC;
            #pragma unroll
            for (int i = 0; i < 7; ++i)
                og[(r0 + i) * DIMC + pc * DH + c] = acc[i];
        }
    }
}

extern "C" void kernel_launch(void* const* d_in, const int* in_sizes, int n_in,
                              void* d_out, int out_size) {
    const float* x      = (const float*)d_in[0];
    const float* mask   = (const float*)d_in[1];
    const float* qkv_w  = (const float*)d_in[2];
    const float* qkv_b  = (const float*)d_in[3];
    const float* proj_w = (const float*)d_in[4];
    const float* proj_b = (const float*)d_in[5];
    const float* rpbt   = (const float*)d_in[6];
    const int*   relidx = (const int*)d_in[7];
    float* out = (float*)d_out;

    const int smem_bytes = (int)sizeof(SM);
    cudaFuncSetAttribute(window_attn_fused,
                         cudaFuncAttributeMaxDynamicSharedMemorySize, smem_bytes);

    window_attn_fused<<<BWIN, 256, smem_bytes>>>(
        x, mask, qkv_w, qkv_b, proj_w, proj_b, rpbt, relidx, out);
}